// round 7
// baseline (speedup 1.0000x reference)
#include <cuda_runtime.h>
#include <cstdint>

#define BATCH 8
#define CC    64
#define CQ    8
#define NN_   4096
#define TMC   128          // m-rows per CTA (8 warps x 16)
#define TN    64           // n-tile
#define NT    (NN_ / TN)
#define THREADS 256

typedef unsigned long long ull;

// Scratch (device globals; no allocation allowed)
__device__ float g_f [(size_t)BATCH * NN_ * CQ];   // keys  [B][N][8], pre-scaled log2e
__device__ float g_g [(size_t)BATCH * NN_ * CQ];   // query [B][N][8]
__device__ float g_hT[(size_t)BATCH * CC * NN_];   // values transposed [B][C][N]

// ---------------------------------------------------------------- helpers
__device__ __forceinline__ uint32_t smem_u32(const void* p) {
    uint32_t a;
    asm("{ .reg .u64 t; cvta.to.shared.u64 t, %1; cvt.u32.u64 %0, t; }"
        : "=r"(a) : "l"(p));
    return a;
}
#define CPA16(dst, src) \
    asm volatile("cp.async.cg.shared.global [%0], [%1], 16;" \
                 :: "r"(dst), "l"(__cvta_generic_to_global(src)))
#define CPCOMMIT() asm volatile("cp.async.commit_group;" ::: "memory")
#define CPWAIT0()  asm volatile("cp.async.wait_group 0;" ::: "memory")

__device__ __forceinline__ void ldsm4(uint32_t& r0, uint32_t& r1,
                                      uint32_t& r2, uint32_t& r3, uint32_t a) {
    asm volatile("ldmatrix.sync.aligned.m8n8.x4.shared.b16 {%0,%1,%2,%3}, [%4];"
                 : "=r"(r0), "=r"(r1), "=r"(r2), "=r"(r3) : "r"(a));
}
__device__ __forceinline__ void mma8(float* d, const uint32_t* a,
                                     uint32_t b0, uint32_t b1) {
    asm volatile("mma.sync.aligned.m16n8k8.row.col.f32.tf32.tf32.f32 "
                 "{%0,%1,%2,%3},{%4,%5,%6,%7},{%8,%9},{%0,%1,%2,%3};"
                 : "+f"(d[0]), "+f"(d[1]), "+f"(d[2]), "+f"(d[3])
                 : "r"(a[0]), "r"(a[1]), "r"(a[2]), "r"(a[3]), "r"(b0), "r"(b1));
}
#define STS64(addr, v) \
    asm volatile("st.shared.b64 [%0], %1;" :: "r"(addr), "l"(v) : "memory")

// ---- packed f32x2 ----
__device__ __forceinline__ ull pack2f(float a, float b) {
    ull r; asm("mov.b64 %0, {%1, %2};" : "=l"(r) : "f"(a), "f"(b)); return r;
}
__device__ __forceinline__ void unpack2f(ull v, float& a, float& b) {
    asm("mov.b64 {%0, %1}, %2;" : "=f"(a), "=f"(b) : "l"(v));
}
__device__ __forceinline__ ull ffma2(ull a, ull b, ull c) {
    ull d; asm("fma.rn.f32x2 %0, %1, %2, %3;" : "=l"(d) : "l"(a), "l"(b), "l"(c)); return d;
}
__device__ __forceinline__ ull add2(ull a, ull b) {
    ull d; asm("add.rn.f32x2 %0, %1, %2;" : "=l"(d) : "l"(a), "l"(b)); return d;
}
// exp2 on a packed pair of pre-scaled scores. Degree-4: remainder ~4e-5,
// far below the tf32 quantization the weights see inside the HMMA.
__device__ __forceinline__ ull exp2_pair(ull s2) {
    const ull MAGIC2    = pack2f(12582912.0f, 12582912.0f);
    const ull NEGMAGIC2 = pack2f(-12582912.0f, -12582912.0f);
    const ull NEGONE2   = pack2f(-1.0f, -1.0f);
    const ull K0 = pack2f(1.0f, 1.0f);
    const ull K1 = pack2f(0.69314718056f, 0.69314718056f);
    const ull K2 = pack2f(0.240226506959f, 0.240226506959f);
    const ull K3 = pack2f(0.0555041086648f, 0.0555041086648f);
    const ull K4 = pack2f(0.00961812910763f, 0.00961812910763f);
    ull t2 = add2(s2, MAGIC2);
    ull kf = add2(t2, NEGMAGIC2);
    ull r2 = ffma2(kf, NEGONE2, s2);
    ull p2 = ffma2(K4, r2, K3);
    p2 = ffma2(p2, r2, K2);
    p2 = ffma2(p2, r2, K1);
    p2 = ffma2(p2, r2, K0);
    uint32_t tlo = (uint32_t)t2, thi = (uint32_t)(t2 >> 32);
    uint32_t plo = (uint32_t)p2, phi = (uint32_t)(p2 >> 32);
    return (ull)(plo + (tlo << 23)) | ((ull)(phi + (thi << 23)) << 32);
}

// ============================================================================
// Kernel 1: projections. x:[B,64,N] -> f:[B,N,8] (x log2e), g:[B,N,8], hT:[B,64,N]
// ============================================================================
__global__ __launch_bounds__(128) void proj_kernel(
    const float* __restrict__ x,
    const float* __restrict__ Wq, const float* __restrict__ bq,
    const float* __restrict__ Wk, const float* __restrict__ bk,
    const float* __restrict__ Wv, const float* __restrict__ bv)
{
    __shared__ float sWq[CQ * CC], sWk[CQ * CC], sWv[CC * CC];
    __shared__ float sbq[CQ], sbk[CQ], sbv[CC];
    int t = threadIdx.x;
    for (int i = t; i < CQ * CC; i += 128) { sWq[i] = Wq[i]; sWk[i] = Wk[i]; }
    for (int i = t; i < CC * CC; i += 128) sWv[i] = Wv[i];
    if (t < CQ) { sbq[t] = bq[t]; sbk[t] = bk[t]; }
    if (t < CC) sbv[t] = bv[t];
    __syncthreads();

    int b = blockIdx.x / (NN_ / 128);
    int n = (blockIdx.x % (NN_ / 128)) * 128 + t;

    float xv[CC];
    const float* xb = x + ((size_t)b * CC) * NN_ + n;
    #pragma unroll
    for (int c = 0; c < CC; c++) xv[c] = xb[(size_t)c * NN_];

    const float LOG2E = 1.4426950408889634f;
    size_t base = (size_t)b * NN_ + n;

    #pragma unroll 2
    for (int d = 0; d < CQ; d++) {
        float af = sbq[d], ag = sbk[d];
        #pragma unroll
        for (int c = 0; c < CC; c++) {
            af = fmaf(sWq[d * CC + c], xv[c], af);
            ag = fmaf(sWk[d * CC + c], xv[c], ag);
        }
        g_f[base * CQ + d] = af * LOG2E;
        g_g[base * CQ + d] = ag;
    }
    #pragma unroll 4
    for (int o = 0; o < CC; o++) {
        float a = sbv[o];
        #pragma unroll
        for (int c = 0; c < CC; c++) a = fmaf(sWv[o * CC + c], xv[c], a);
        g_hT[((size_t)b * CC + o) * NN_ + n] = a;
    }
}

// ============================================================================
// Kernel 2: flash attention on mma.sync tf32, 8 independent warps.
//   warp w: owns m-rows [mt+16w, mt+16w+16), full n and full c.
//   GEMM1: S[16m x 64n] (K=8). exp2 -> warp-PRIVATE W patch (syncwarp only).
//   GEMM2: O[16m x 64c] += W x H (K=64). One CTA barrier per tile.
// ============================================================================
#define HSTR   272
#define FSTR   48
#define WSTR   272
#define OFF_H0 0
#define OFF_H1 17408
#define OFF_F0 34816
#define OFF_F1 37888
#define OFF_W  40960
#define WSZ    4352                  // 16 rows * 272
#define SMEM_SZ (OFF_W + 8 * WSZ)    // 75776

__global__ __launch_bounds__(THREADS, 2) void attn_kernel(
    const float* __restrict__ x,
    const float* __restrict__ gamma,
    float* __restrict__ out)
{
    extern __shared__ __align__(128) char smem[];
    uint32_t sb = smem_u32(smem);

    int t = threadIdx.x;
    int wid = t >> 5, lane = t & 31;
    int grp = lane >> 3, row8 = lane & 7;
    int b  = blockIdx.x >> 5;
    int mt = (blockIdx.x & 31) * TMC;
    int mw = mt + wid * 16;

    // LDSM per-lane base offsets
    uint32_t off_f = ((grp >> 1) * 8 + row8) * FSTR + (grp & 1) * 16;
    uint32_t off_h = ((grp >> 1) * 8 + row8) * HSTR + (grp & 1) * 16;
    uint32_t off_w = ((grp & 1) * 8 + row8) * WSTR + (grp >> 1) * 16;
    uint32_t wbase = sb + OFF_W + wid * WSZ;
    uint32_t wld   = wbase + off_w;
    uint32_t wst   = wbase + (lane >> 2) * WSTR + (lane & 3) * 8;

    // G fragment (A operand, one m16 block, K=8)
    uint32_t ga[4];
    {
        const float* gb = g_g + ((size_t)b * NN_) * CQ;
        int r = lane >> 2, k = lane & 3;
        ga[0] = __float_as_uint(gb[(size_t)(mw + r)     * CQ + k]);
        ga[1] = __float_as_uint(gb[(size_t)(mw + r + 8) * CQ + k]);
        ga[2] = __float_as_uint(gb[(size_t)(mw + r)     * CQ + k + 4]);
        ga[3] = __float_as_uint(gb[(size_t)(mw + r + 8) * CQ + k + 4]);
    }

    float acc[8][4];
    #pragma unroll
    for (int c = 0; c < 8; c++)
        #pragma unroll
        for (int i = 0; i < 4; i++) acc[c][i] = 0.0f;
    ull l2[2] = {0ULL, 0ULL};   // [row r, row r+8] partial sums (2 cols packed)

    const float* hsrc0 = g_hT + (size_t)b * CC * NN_;
    const float* fsrc0 = g_f + (size_t)b * NN_ * CQ;

    auto load_tile = [&](int it) {
        int n0 = it * TN;
        uint32_t hb = sb + ((it & 1) ? OFF_H1 : OFF_H0);
        uint32_t fb = sb + ((it & 1) ? OFF_F1 : OFF_F0);
        #pragma unroll
        for (int p = 0; p < 4; p++) {
            int cid = t + p * THREADS;
            int row = cid >> 4, col = (cid & 15) * 4;
            CPA16(hb + row * HSTR + col * 4, hsrc0 + (size_t)row * NN_ + n0 + col);
        }
        if (t < 128) {
            int row = t >> 1, half = t & 1;
            CPA16(fb + row * FSTR + half * 16,
                  fsrc0 + (size_t)(n0 + row) * CQ + half * 4);
        }
        CPCOMMIT();
    };

    load_tile(0);

    for (int it = 0; it < NT; it++) {
        CPWAIT0();
        __syncthreads();                      // tile ready; also orders W reuse
        if (it + 1 < NT) load_tile(it + 1);

        uint32_t hb = sb + ((it & 1) ? OFF_H1 : OFF_H0);
        uint32_t fb = sb + ((it & 1) ? OFF_F1 : OFF_F0);

        // ---- GEMM1: S[16m x 64n] ----
        float s[8][4];
        #pragma unroll
        for (int ns = 0; ns < 8; ns++)
            #pragma unroll
            for (int i = 0; i < 4; i++) s[ns][i] = 0.0f;
        #pragma unroll
        for (int np = 0; np < 4; np++) {
            uint32_t b0, b1, b2, b3;
            ldsm4(b0, b1, b2, b3, fb + np * 16 * FSTR + off_f);
            mma8(s[2 * np],     ga, b0, b1);
            mma8(s[2 * np + 1], ga, b2, b3);
        }

        // ---- exp2 + store W into warp-private patch ----
        #pragma unroll
        for (int ns = 0; ns < 8; ns++) {
            ull w01 = exp2_pair(pack2f(s[ns][0], s[ns][1]));   // row r
            ull w23 = exp2_pair(pack2f(s[ns][2], s[ns][3]));   // row r+8
            l2[0] = add2(l2[0], w01);
            l2[1] = add2(l2[1], w23);
            STS64(wst + ns * 32, w01);
            STS64(wst + 8 * WSTR + ns * 32, w23);
        }
        __syncwarp();

        // ---- GEMM2: O[16m x 64c] += W x H, K=64 ----
        #pragma unroll
        for (int ks = 0; ks < 8; ks++) {
            uint32_t a[4];
            ldsm4(a[0], a[1], a[2], a[3], wld + ks * 32);
            #pragma unroll
            for (int cp = 0; cp < 4; cp++) {
                uint32_t r0, r1, r2, r3;
                ldsm4(r0, r1, r2, r3, hb + off_h + cp * 16 * HSTR + ks * 32);
                mma8(acc[2 * cp],     a, r0, r1);
                mma8(acc[2 * cp + 1], a, r2, r3);
            }
        }
    }

    // ---- l reduction: fold packed pair + quad shuffle (warp-local) ----
    float scale0, scale1;
    {
        float gm = gamma[0];
        float lo, hi;
        unpack2f(l2[0], lo, hi);
        float la = lo + hi;
        la += __shfl_xor_sync(0xFFFFFFFF, la, 1);
        la += __shfl_xor_sync(0xFFFFFFFF, la, 2);
        unpack2f(l2[1], lo, hi);
        float lb = lo + hi;
        lb += __shfl_xor_sync(0xFFFFFFFF, lb, 1);
        lb += __shfl_xor_sync(0xFFFFFFFF, lb, 2);
        scale0 = gm / la;
        scale1 = gm / lb;
    }

    // ---- epilogue ----
    const float* xb = x   + (size_t)b * CC * NN_;
    float*       ob = out + (size_t)b * CC * NN_;
    int r = lane >> 2, q = lane & 3;
    int m0 = mw + r;
    #pragma unroll
    for (int cs = 0; cs < 8; cs++) {
        int c = cs * 8 + 2 * q;
        size_t a00 = (size_t)c * NN_ + m0;
        size_t a01 = a00 + NN_;
        ob[a00]     = fmaf(acc[cs][0], scale0, xb[a00]);
        ob[a01]     = fmaf(acc[cs][1], scale0, xb[a01]);
        ob[a00 + 8] = fmaf(acc[cs][2], scale1, xb[a00 + 8]);
        ob[a01 + 8] = fmaf(acc[cs][3], scale1, xb[a01 + 8]);
    }
}

// ============================================================================
extern "C" void kernel_launch(void* const* d_in, const int* in_sizes, int n_in,
                              void* d_out, int out_size)
{
    const float* x     = (const float*)d_in[0];
    const float* Wq    = (const float*)d_in[1];
    const float* bq    = (const float*)d_in[2];
    const float* Wk    = (const float*)d_in[3];
    const float* bk    = (const float*)d_in[4];
    const float* Wv    = (const float*)d_in[5];
    const float* bv    = (const float*)d_in[6];
    const float* gamma = (const float*)d_in[7];
    float* out = (float*)d_out;

    static bool attr_set = false;
    if (!attr_set) {
        cudaFuncSetAttribute(attn_kernel,
                             cudaFuncAttributeMaxDynamicSharedMemorySize, SMEM_SZ);
        attr_set = true;
    }

    proj_kernel<<<BATCH * NN_ / 128, 128>>>(x, Wq, bq, Wk, bk, Wv, bv);
    attn_kernel<<<BATCH * NN_ / TMC, THREADS, SMEM_SZ>>>(x, gamma, out);
}

// round 9
// speedup vs baseline: 1.4302x; 1.4302x over previous
#include <cuda_runtime.h>
#include <cstdint>

#define BATCH 8
#define CC    64
#define CQ    8
#define NN_   4096
#define TMC   128          // m-rows per CTA (8 warps x 16)
#define TN    64           // n-tile
#define NT    (NN_ / TN)
#define THREADS 256

typedef unsigned long long ull;

// fp16 scratch (device globals; no allocation allowed)
__device__ unsigned short g_f16[(size_t)BATCH * NN_ * CQ];  // keys [B][N][8], x log2e
__device__ unsigned short g_g16[(size_t)BATCH * NN_ * CQ];  // query [B][N][8]
__device__ unsigned short g_h16[(size_t)BATCH * NN_ * CC];  // values [B][N][64]

// ---------------------------------------------------------------- helpers
__device__ __forceinline__ uint32_t smem_u32(const void* p) {
    uint32_t a;
    asm("{ .reg .u64 t; cvta.to.shared.u64 t, %1; cvt.u32.u64 %0, t; }"
        : "=r"(a) : "l"(p));
    return a;
}
#define CPA16(dst, src) \
    asm volatile("cp.async.cg.shared.global [%0], [%1], 16;" \
                 :: "r"(dst), "l"(__cvta_generic_to_global(src)))
#define CPCOMMIT() asm volatile("cp.async.commit_group;" ::: "memory")
#define CPWAIT0()  asm volatile("cp.async.wait_group 0;" ::: "memory")

__device__ __forceinline__ void ldsm4(uint32_t& r0, uint32_t& r1,
                                      uint32_t& r2, uint32_t& r3, uint32_t a) {
    asm volatile("ldmatrix.sync.aligned.m8n8.x4.shared.b16 {%0,%1,%2,%3}, [%4];"
                 : "=r"(r0), "=r"(r1), "=r"(r2), "=r"(r3) : "r"(a));
}
__device__ __forceinline__ void ldsm4t(uint32_t& r0, uint32_t& r1,
                                       uint32_t& r2, uint32_t& r3, uint32_t a) {
    asm volatile("ldmatrix.sync.aligned.m8n8.x4.trans.shared.b16 {%0,%1,%2,%3}, [%4];"
                 : "=r"(r0), "=r"(r1), "=r"(r2), "=r"(r3) : "r"(a));
}
// f16 MMA, K=8: S += G x F^T
__device__ __forceinline__ void mma_k8(float* d, uint32_t a0, uint32_t a1,
                                       uint32_t b0) {
    asm volatile("mma.sync.aligned.m16n8k8.row.col.f32.f16.f16.f32 "
                 "{%0,%1,%2,%3},{%4,%5},{%6},{%0,%1,%2,%3};"
                 : "+f"(d[0]), "+f"(d[1]), "+f"(d[2]), "+f"(d[3])
                 : "r"(a0), "r"(a1), "r"(b0));
}
// f16 MMA, K=16: O += W x H
__device__ __forceinline__ void mma_k16(float* d, const uint32_t* a,
                                        uint32_t b0, uint32_t b1) {
    asm volatile("mma.sync.aligned.m16n8k16.row.col.f32.f16.f16.f32 "
                 "{%0,%1,%2,%3},{%4,%5,%6,%7},{%8,%9},{%0,%1,%2,%3};"
                 : "+f"(d[0]), "+f"(d[1]), "+f"(d[2]), "+f"(d[3])
                 : "r"(a[0]), "r"(a[1]), "r"(a[2]), "r"(a[3]), "r"(b0), "r"(b1));
}
__device__ __forceinline__ uint32_t h2pack(float lo, float hi) {
    uint32_t r;
    asm("cvt.rn.f16x2.f32 %0, %1, %2;" : "=r"(r) : "f"(hi), "f"(lo));
    return r;
}

// ---- packed f32x2 ----
__device__ __forceinline__ ull pack2f(float a, float b) {
    ull r; asm("mov.b64 %0, {%1, %2};" : "=l"(r) : "f"(a), "f"(b)); return r;
}
__device__ __forceinline__ void unpack2f(ull v, float& a, float& b) {
    asm("mov.b64 {%0, %1}, %2;" : "=f"(a), "=f"(b) : "l"(v));
}
__device__ __forceinline__ ull ffma2(ull a, ull b, ull c) {
    ull d; asm("fma.rn.f32x2 %0, %1, %2, %3;" : "=l"(d) : "l"(a), "l"(b), "l"(c)); return d;
}
__device__ __forceinline__ ull add2(ull a, ull b) {
    ull d; asm("add.rn.f32x2 %0, %1, %2;" : "=l"(d) : "l"(a), "l"(b)); return d;
}
__device__ __forceinline__ ull mul2(ull a, ull b) {
    ull d; asm("mul.rn.f32x2 %0, %1, %2;" : "=l"(d) : "l"(a), "l"(b)); return d;
}
// exp2 on a packed pair, args expected in [-126, 0] (max-shifted scores)
__device__ __forceinline__ ull exp2_pair(ull s2) {
    const ull MAGIC2    = pack2f(12582912.0f, 12582912.0f);
    const ull NEGMAGIC2 = pack2f(-12582912.0f, -12582912.0f);
    const ull NEGONE2   = pack2f(-1.0f, -1.0f);
    const ull K0 = pack2f(1.0f, 1.0f);
    const ull K1 = pack2f(0.69314718056f, 0.69314718056f);
    const ull K2 = pack2f(0.240226506959f, 0.240226506959f);
    const ull K3 = pack2f(0.0555041086648f, 0.0555041086648f);
    const ull K4 = pack2f(0.00961812910763f, 0.00961812910763f);
    ull t2 = add2(s2, MAGIC2);
    ull kf = add2(t2, NEGMAGIC2);
    ull r2 = ffma2(kf, NEGONE2, s2);
    ull p2 = ffma2(K4, r2, K3);
    p2 = ffma2(p2, r2, K2);
    p2 = ffma2(p2, r2, K1);
    p2 = ffma2(p2, r2, K0);
    uint32_t tlo = (uint32_t)t2, thi = (uint32_t)(t2 >> 32);
    uint32_t plo = (uint32_t)p2, phi = (uint32_t)(p2 >> 32);
    return (ull)(plo + (tlo << 23)) | ((ull)(phi + (thi << 23)) << 32);
}
// scalar exp2, clamped (safe for first-tile -1e30 diffs)
__device__ __forceinline__ float exp2s(float d) {
    d = fmaxf(d, -126.0f);
    float t = d + 12582912.0f;
    float r = d - (t - 12582912.0f);
    float p = fmaf(0.00961812910763f, r, 0.0555041086648f);
    p = fmaf(p, r, 0.240226506959f);
    p = fmaf(p, r, 0.69314718056f);
    p = fmaf(p, r, 1.0f);
    return __uint_as_float(__float_as_uint(p) + (__float_as_uint(t) << 23));
}

// ============================================================================
// Kernel 1: projections -> fp16. f:[B,N,8] (x log2e), g:[B,N,8], h:[B,N,64]
// ============================================================================
__global__ __launch_bounds__(128) void proj_kernel(
    const float* __restrict__ x,
    const float* __restrict__ Wq, const float* __restrict__ bq,
    const float* __restrict__ Wk, const float* __restrict__ bk,
    const float* __restrict__ Wv, const float* __restrict__ bv)
{
    __shared__ float sWq[CQ * CC], sWk[CQ * CC], sWv[CC * CC];
    __shared__ float sbq[CQ], sbk[CQ], sbv[CC];
    int t = threadIdx.x;
    for (int i = t; i < CQ * CC; i += 128) { sWq[i] = Wq[i]; sWk[i] = Wk[i]; }
    for (int i = t; i < CC * CC; i += 128) sWv[i] = Wv[i];
    if (t < CQ) { sbq[t] = bq[t]; sbk[t] = bk[t]; }
    if (t < CC) sbv[t] = bv[t];
    __syncthreads();

    int b = blockIdx.x / (NN_ / 128);
    int n = (blockIdx.x % (NN_ / 128)) * 128 + t;

    float xv[CC];
    const float* xb = x + ((size_t)b * CC) * NN_ + n;
    #pragma unroll
    for (int c = 0; c < CC; c++) xv[c] = xb[(size_t)c * NN_];

    const float LOG2E = 1.4426950408889634f;
    size_t base = (size_t)b * NN_ + n;

    {
        float af[CQ], ag[CQ];
        #pragma unroll
        for (int d = 0; d < CQ; d++) {
            float vf = sbq[d], vg = sbk[d];
            #pragma unroll
            for (int c = 0; c < CC; c++) {
                vf = fmaf(sWq[d * CC + c], xv[c], vf);
                vg = fmaf(sWk[d * CC + c], xv[c], vg);
            }
            af[d] = vf * LOG2E;
            ag[d] = vg;
        }
        uint4 uf, ug;
        uf.x = h2pack(af[0], af[1]); uf.y = h2pack(af[2], af[3]);
        uf.z = h2pack(af[4], af[5]); uf.w = h2pack(af[6], af[7]);
        ug.x = h2pack(ag[0], ag[1]); ug.y = h2pack(ag[2], ag[3]);
        ug.z = h2pack(ag[4], ag[5]); ug.w = h2pack(ag[6], ag[7]);
        *(uint4*)(g_f16 + base * CQ) = uf;
        *(uint4*)(g_g16 + base * CQ) = ug;
    }

    #pragma unroll
    for (int grp = 0; grp < 8; grp++) {
        float hv[8];
        #pragma unroll
        for (int j = 0; j < 8; j++) {
            int o = grp * 8 + j;
            float a = sbv[o];
            #pragma unroll
            for (int c = 0; c < CC; c++) a = fmaf(sWv[o * CC + c], xv[c], a);
            hv[j] = a;
        }
        uint4 u;
        u.x = h2pack(hv[0], hv[1]); u.y = h2pack(hv[2], hv[3]);
        u.z = h2pack(hv[4], hv[5]); u.w = h2pack(hv[6], hv[7]);
        *(uint4*)(g_h16 + base * CC + grp * 8) = u;
    }
}

// ============================================================================
// Kernel 2: fp16 flash attention with FA2 running max, W never touches smem.
//   8 independent warps x 16m. Per 64-n tile:
//     GEMM1 f16 k8: S[16m x 64n]; per-row tile max -> running max + rescale
//     w = exp2(s - m) in (0,1] -> fp16 A-frags (register identity, no STS)
//     GEMM2 f16 k16: O += W x H (H fp16, ldsm.trans)
// ============================================================================
#define HSTR   144
#define H_TILE (64 * HSTR)          // 9216
#define OFF_H0 0
#define OFF_H1 H_TILE
#define OFF_F0 (2 * H_TILE)
#define OFF_F1 (2 * H_TILE + 1024)
#define SMEM_SZ (2 * H_TILE + 2048) // 20480

__global__ __launch_bounds__(THREADS, 2) void attn_kernel(
    const float* __restrict__ x,
    const float* __restrict__ gamma,
    float* __restrict__ out)
{
    __shared__ __align__(128) char smem[SMEM_SZ];
    uint32_t sb = smem_u32(smem);

    int t = threadIdx.x;
    int wid = t >> 5, lane = t & 31;
    int b  = blockIdx.x >> 5;
    int mt = (blockIdx.x & 31) * TMC;
    int mw = mt + wid * 16;
    int r = lane >> 2, q = lane & 3;

    uint32_t hoff = (uint32_t)((lane & 15) * HSTR + (lane >> 4) * 16);

    uint32_t ga0, ga1;
    {
        const uint32_t* gp =
            (const uint32_t*)(g_g16 + ((size_t)b * NN_ + mw) * CQ);
        ga0 = gp[r * 4 + q];
        ga1 = gp[(r + 8) * 4 + q];
    }

    float acc[8][4];
    #pragma unroll
    for (int c = 0; c < 8; c++)
        #pragma unroll
        for (int i = 0; i < 4; i++) acc[c][i] = 0.0f;
    ull l2[2] = {0ULL, 0ULL};
    float m0 = -1e30f, m1 = -1e30f;   // running row maxes (rows r, r+8)

    const unsigned short* hsrc0 = g_h16 + (size_t)b * NN_ * CC;
    const unsigned short* fsrc0 = g_f16 + (size_t)b * NN_ * CQ;

    auto load_tile = [&](int it) {
        int n0 = it * TN;
        uint32_t hb = sb + ((it & 1) ? OFF_H1 : OFF_H0);
        uint32_t fb = sb + ((it & 1) ? OFF_F1 : OFF_F0);
        #pragma unroll
        for (int p = 0; p < 2; p++) {
            int id = t + p * THREADS;
            int row = id >> 3, ch = id & 7;
            CPA16(hb + row * HSTR + ch * 16,
                  hsrc0 + ((size_t)(n0 + row)) * CC + ch * 8);
        }
        if (t < 64)
            CPA16(fb + t * 16, fsrc0 + ((size_t)(n0 + t)) * CQ);
        CPCOMMIT();
    };

    load_tile(0);

    for (int it = 0; it < NT; it++) {
        CPWAIT0();
        __syncthreads();
        if (it + 1 < NT) load_tile(it + 1);

        uint32_t hb = sb + ((it & 1) ? OFF_H1 : OFF_H0);
        uint32_t fb = sb + ((it & 1) ? OFF_F1 : OFF_F0);

        // ---- GEMM1: S[16m x 64n], f16 K=8 ----
        uint32_t fbr[8];
        ldsm4(fbr[0], fbr[1], fbr[2], fbr[3], fb + lane * 16);
        ldsm4(fbr[4], fbr[5], fbr[6], fbr[7], fb + 512 + lane * 16);
        float s[8][4];
        #pragma unroll
        for (int j = 0; j < 8; j++) {
            #pragma unroll
            for (int i = 0; i < 4; i++) s[j][i] = 0.0f;
            mma_k8(s[j], ga0, ga1, fbr[j]);
        }

        // ---- per-row tile max -> running max + rescale ----
        float t0 = -1e30f, t1 = -1e30f;
        #pragma unroll
        for (int j = 0; j < 8; j++) {
            t0 = fmaxf(t0, fmaxf(s[j][0], s[j][1]));
            t1 = fmaxf(t1, fmaxf(s[j][2], s[j][3]));
        }
        t0 = fmaxf(t0, __shfl_xor_sync(0xFFFFFFFF, t0, 1));
        t0 = fmaxf(t0, __shfl_xor_sync(0xFFFFFFFF, t0, 2));
        t1 = fmaxf(t1, __shfl_xor_sync(0xFFFFFFFF, t1, 1));
        t1 = fmaxf(t1, __shfl_xor_sync(0xFFFFFFFF, t1, 2));
        float m0n = fmaxf(m0, t0);
        float m1n = fmaxf(m1, t1);
        float sc0 = exp2s(m0 - m0n);
        float sc1 = exp2s(m1 - m1n);
        m0 = m0n; m1 = m1n;
        l2[0] = mul2(l2[0], pack2f(sc0, sc0));
        l2[1] = mul2(l2[1], pack2f(sc1, sc1));
        #pragma unroll
        for (int c = 0; c < 8; c++) {
            acc[c][0] *= sc0; acc[c][1] *= sc0;
            acc[c][2] *= sc1; acc[c][3] *= sc1;
        }

        // ---- exp2(s - m) -> fp16 A-fragments in registers ----
        ull nm0 = pack2f(-m0n, -m0n);
        ull nm1 = pack2f(-m1n, -m1n);
        uint32_t af[4][4];
        #pragma unroll
        for (int tk = 0; tk < 4; tk++) {
            #pragma unroll
            for (int u = 0; u < 2; u++) {
                int j = 2 * tk + u;
                ull w01 = exp2_pair(add2(pack2f(s[j][0], s[j][1]), nm0));
                ull w23 = exp2_pair(add2(pack2f(s[j][2], s[j][3]), nm1));
                l2[0] = add2(l2[0], w01);
                l2[1] = add2(l2[1], w23);
                float wa, wb;
                unpack2f(w01, wa, wb);
                af[tk][2 * u]     = h2pack(wa, wb);
                unpack2f(w23, wa, wb);
                af[tk][2 * u + 1] = h2pack(wa, wb);
            }
        }

        // ---- GEMM2: O += W x H, f16 K=16, H via ldsm.trans ----
        #pragma unroll
        for (int tk = 0; tk < 4; tk++) {
            uint32_t hbase = hb + tk * 16 * HSTR + hoff;
            #pragma unroll
            for (int cb = 0; cb < 4; cb++) {
                uint32_t b0, b1, b2, b3;
                ldsm4t(b0, b1, b2, b3, hbase + cb * 32);
                mma_k16(acc[2 * cb],     af[tk], b0, b1);
                mma_k16(acc[2 * cb + 1], af[tk], b2, b3);
            }
        }
    }

    // ---- l reduction (warp-local quad) ----
    float scale0, scale1;
    {
        float gm = gamma[0];
        float lo, hi;
        unpack2f(l2[0], lo, hi);
        float la = lo + hi;
        la += __shfl_xor_sync(0xFFFFFFFF, la, 1);
        la += __shfl_xor_sync(0xFFFFFFFF, la, 2);
        unpack2f(l2[1], lo, hi);
        float lb = lo + hi;
        lb += __shfl_xor_sync(0xFFFFFFFF, lb, 1);
        lb += __shfl_xor_sync(0xFFFFFFFF, lb, 2);
        scale0 = gm / la;
        scale1 = gm / lb;
    }

    // ---- epilogue ----
    const float* xb = x   + (size_t)b * CC * NN_;
    float*       ob = out + (size_t)b * CC * NN_;
    int m0g = mw + r;
    #pragma unroll
    for (int cs = 0; cs < 8; cs++) {
        int c = cs * 8 + 2 * q;
        size_t a00 = (size_t)c * NN_ + m0g;
        size_t a01 = a00 + NN_;
        ob[a00]     = fmaf(acc[cs][0], scale0, xb[a00]);
        ob[a01]     = fmaf(acc[cs][1], scale0, xb[a01]);
        ob[a00 + 8] = fmaf(acc[cs][2], scale1, xb[a00 + 8]);
        ob[a01 + 8] = fmaf(acc[cs][3], scale1, xb[a01 + 8]);
    }
}

// ============================================================================
extern "C" void kernel_launch(void* const* d_in, const int* in_sizes, int n_in,
                              void* d_out, int out_size)
{
    const float* x     = (const float*)d_in[0];
    const float* Wq    = (const float*)d_in[1];
    const float* bq    = (const float*)d_in[2];
    const float* Wk    = (const float*)d_in[3];
    const float* bk    = (const float*)d_in[4];
    const float* Wv    = (const float*)d_in[5];
    const float* bv    = (const float*)d_in[6];
    const float* gamma = (const float*)d_in[7];
    float* out = (float*)d_out;

    proj_kernel<<<BATCH * NN_ / 128, 128>>>(x, Wq, bq, Wk, bk, Wv, bv);
    attn_kernel<<<BATCH * NN_ / TMC, THREADS>>>(x, gamma, out);
}

// round 10
// speedup vs baseline: 1.5539x; 1.0865x over previous
#include <cuda_runtime.h>
#include <cstdint>

#define BATCH 8
#define CC    64
#define CQ    8
#define NN_   4096
#define TMC   128          // m-rows per CTA (8 warps x 16)
#define TN    64           // n-tile
#define NT    (NN_ / TN)
#define THREADS 256

typedef unsigned long long ull;

// fp16 scratch (device globals; no allocation allowed)
__device__ unsigned short g_f16[(size_t)BATCH * NN_ * CQ];  // keys [B][N][8], x log2e
__device__ unsigned short g_g16[(size_t)BATCH * NN_ * CQ];  // query [B][N][8]
__device__ unsigned short g_h16[(size_t)BATCH * NN_ * CC];  // values [B][N][64]

// ---------------------------------------------------------------- helpers
__device__ __forceinline__ uint32_t smem_u32(const void* p) {
    uint32_t a;
    asm("{ .reg .u64 t; cvta.to.shared.u64 t, %1; cvt.u32.u64 %0, t; }"
        : "=r"(a) : "l"(p));
    return a;
}
#define CPA16(dst, src) \
    asm volatile("cp.async.cg.shared.global [%0], [%1], 16;" \
                 :: "r"(dst), "l"(__cvta_generic_to_global(src)))
#define CPCOMMIT() asm volatile("cp.async.commit_group;" ::: "memory")
#define CPWAIT0()  asm volatile("cp.async.wait_group 0;" ::: "memory")

__device__ __forceinline__ void ldsm4(uint32_t& r0, uint32_t& r1,
                                      uint32_t& r2, uint32_t& r3, uint32_t a) {
    asm volatile("ldmatrix.sync.aligned.m8n8.x4.shared.b16 {%0,%1,%2,%3}, [%4];"
                 : "=r"(r0), "=r"(r1), "=r"(r2), "=r"(r3) : "r"(a));
}
__device__ __forceinline__ void ldsm4t(uint32_t& r0, uint32_t& r1,
                                       uint32_t& r2, uint32_t& r3, uint32_t a) {
    asm volatile("ldmatrix.sync.aligned.m8n8.x4.trans.shared.b16 {%0,%1,%2,%3}, [%4];"
                 : "=r"(r0), "=r"(r1), "=r"(r2), "=r"(r3) : "r"(a));
}
// f16 MMA, K=8: S += G x F^T
__device__ __forceinline__ void mma_k8(float* d, uint32_t a0, uint32_t a1,
                                       uint32_t b0) {
    asm volatile("mma.sync.aligned.m16n8k8.row.col.f32.f16.f16.f32 "
                 "{%0,%1,%2,%3},{%4,%5},{%6},{%0,%1,%2,%3};"
                 : "+f"(d[0]), "+f"(d[1]), "+f"(d[2]), "+f"(d[3])
                 : "r"(a0), "r"(a1), "r"(b0));
}
// f16 MMA, K=16: O += W x H
__device__ __forceinline__ void mma_k16(float* d, const uint32_t* a,
                                        uint32_t b0, uint32_t b1) {
    asm volatile("mma.sync.aligned.m16n8k16.row.col.f32.f16.f16.f32 "
                 "{%0,%1,%2,%3},{%4,%5,%6,%7},{%8,%9},{%0,%1,%2,%3};"
                 : "+f"(d[0]), "+f"(d[1]), "+f"(d[2]), "+f"(d[3])
                 : "r"(a[0]), "r"(a[1]), "r"(a[2]), "r"(a[3]), "r"(b0), "r"(b1));
}
__device__ __forceinline__ uint32_t h2pack(float lo, float hi) {
    uint32_t r;
    asm("cvt.rn.f16x2.f32 %0, %1, %2;" : "=r"(r) : "f"(hi), "f"(lo));
    return r;
}

// ---- packed f32x2 ----
__device__ __forceinline__ ull pack2f(float a, float b) {
    ull r; asm("mov.b64 %0, {%1, %2};" : "=l"(r) : "f"(a), "f"(b)); return r;
}
__device__ __forceinline__ void unpack2f(ull v, float& a, float& b) {
    asm("mov.b64 {%0, %1}, %2;" : "=f"(a), "=f"(b) : "l"(v));
}
__device__ __forceinline__ ull ffma2(ull a, ull b, ull c) {
    ull d; asm("fma.rn.f32x2 %0, %1, %2, %3;" : "=l"(d) : "l"(a), "l"(b), "l"(c)); return d;
}
__device__ __forceinline__ ull add2(ull a, ull b) {
    ull d; asm("add.rn.f32x2 %0, %1, %2;" : "=l"(d) : "l"(a), "l"(b)); return d;
}
__device__ __forceinline__ ull mul2(ull a, ull b) {
    ull d; asm("mul.rn.f32x2 %0, %1, %2;" : "=l"(d) : "l"(a), "l"(b)); return d;
}
// exp2 on a packed pair, args in [-126, ~9] (max-shifted scores with slack)
__device__ __forceinline__ ull exp2_pair(ull s2) {
    const ull MAGIC2    = pack2f(12582912.0f, 12582912.0f);
    const ull NEGMAGIC2 = pack2f(-12582912.0f, -12582912.0f);
    const ull NEGONE2   = pack2f(-1.0f, -1.0f);
    const ull K0 = pack2f(1.0f, 1.0f);
    const ull K1 = pack2f(0.69314718056f, 0.69314718056f);
    const ull K2 = pack2f(0.240226506959f, 0.240226506959f);
    const ull K3 = pack2f(0.0555041086648f, 0.0555041086648f);
    const ull K4 = pack2f(0.00961812910763f, 0.00961812910763f);
    ull t2 = add2(s2, MAGIC2);
    ull kf = add2(t2, NEGMAGIC2);
    ull r2 = ffma2(kf, NEGONE2, s2);
    ull p2 = ffma2(K4, r2, K3);
    p2 = ffma2(p2, r2, K2);
    p2 = ffma2(p2, r2, K1);
    p2 = ffma2(p2, r2, K0);
    uint32_t tlo = (uint32_t)t2, thi = (uint32_t)(t2 >> 32);
    uint32_t plo = (uint32_t)p2, phi = (uint32_t)(p2 >> 32);
    return (ull)(plo + (tlo << 23)) | ((ull)(phi + (thi << 23)) << 32);
}
// scalar exp2, clamped (safe for first-tile -1e30 diffs)
__device__ __forceinline__ float exp2s(float d) {
    d = fmaxf(d, -126.0f);
    float t = d + 12582912.0f;
    float r = d - (t - 12582912.0f);
    float p = fmaf(0.00961812910763f, r, 0.0555041086648f);
    p = fmaf(p, r, 0.240226506959f);
    p = fmaf(p, r, 0.69314718056f);
    p = fmaf(p, r, 1.0f);
    return __uint_as_float(__float_as_uint(p) + (__float_as_uint(t) << 23));
}

// ============================================================================
// Kernel 1: projections -> fp16 (float4-vectorized weight LDS)
// ============================================================================
__global__ __launch_bounds__(128) void proj_kernel(
    const float* __restrict__ x,
    const float* __restrict__ Wq, const float* __restrict__ bq,
    const float* __restrict__ Wk, const float* __restrict__ bk,
    const float* __restrict__ Wv, const float* __restrict__ bv)
{
    __shared__ __align__(16) float sWq[CQ * CC], sWk[CQ * CC], sWv[CC * CC];
    __shared__ float sbq[CQ], sbk[CQ], sbv[CC];
    int t = threadIdx.x;
    for (int i = t; i < CQ * CC; i += 128) { sWq[i] = Wq[i]; sWk[i] = Wk[i]; }
    for (int i = t; i < CC * CC; i += 128) sWv[i] = Wv[i];
    if (t < CQ) { sbq[t] = bq[t]; sbk[t] = bk[t]; }
    if (t < CC) sbv[t] = bv[t];
    __syncthreads();

    int b = blockIdx.x / (NN_ / 128);
    int n = (blockIdx.x % (NN_ / 128)) * 128 + t;

    float xv[CC];
    const float* xb = x + ((size_t)b * CC) * NN_ + n;
    #pragma unroll
    for (int c = 0; c < CC; c++) xv[c] = xb[(size_t)c * NN_];

    const float LOG2E = 1.4426950408889634f;
    size_t base = (size_t)b * NN_ + n;

    {
        float af[CQ], ag[CQ];
        #pragma unroll
        for (int d = 0; d < CQ; d++) {
            float vf = sbq[d], vg = sbk[d];
            const float4* wq4 = (const float4*)&sWq[d * CC];
            const float4* wk4 = (const float4*)&sWk[d * CC];
            #pragma unroll
            for (int c4 = 0; c4 < CC / 4; c4++) {
                float4 wq = wq4[c4], wk = wk4[c4];
                vf = fmaf(wq.x, xv[4 * c4],     vf);
                vf = fmaf(wq.y, xv[4 * c4 + 1], vf);
                vf = fmaf(wq.z, xv[4 * c4 + 2], vf);
                vf = fmaf(wq.w, xv[4 * c4 + 3], vf);
                vg = fmaf(wk.x, xv[4 * c4],     vg);
                vg = fmaf(wk.y, xv[4 * c4 + 1], vg);
                vg = fmaf(wk.z, xv[4 * c4 + 2], vg);
                vg = fmaf(wk.w, xv[4 * c4 + 3], vg);
            }
            af[d] = vf * LOG2E;
            ag[d] = vg;
        }
        uint4 uf, ug;
        uf.x = h2pack(af[0], af[1]); uf.y = h2pack(af[2], af[3]);
        uf.z = h2pack(af[4], af[5]); uf.w = h2pack(af[6], af[7]);
        ug.x = h2pack(ag[0], ag[1]); ug.y = h2pack(ag[2], ag[3]);
        ug.z = h2pack(ag[4], ag[5]); ug.w = h2pack(ag[6], ag[7]);
        *(uint4*)(g_f16 + base * CQ) = uf;
        *(uint4*)(g_g16 + base * CQ) = ug;
    }

    #pragma unroll
    for (int grp = 0; grp < 8; grp++) {
        float hv[8];
        #pragma unroll
        for (int j = 0; j < 8; j++) {
            int o = grp * 8 + j;
            float a = sbv[o];
            const float4* wv4 = (const float4*)&sWv[o * CC];
            #pragma unroll
            for (int c4 = 0; c4 < CC / 4; c4++) {
                float4 wv = wv4[c4];
                a = fmaf(wv.x, xv[4 * c4],     a);
                a = fmaf(wv.y, xv[4 * c4 + 1], a);
                a = fmaf(wv.z, xv[4 * c4 + 2], a);
                a = fmaf(wv.w, xv[4 * c4 + 3], a);
            }
            hv[j] = a;
        }
        uint4 u;
        u.x = h2pack(hv[0], hv[1]); u.y = h2pack(hv[2], hv[3]);
        u.z = h2pack(hv[4], hv[5]); u.w = h2pack(hv[6], hv[7]);
        *(uint4*)(g_h16 + base * CC + grp * 8) = u;
    }
}

// ============================================================================
// Kernel 2: fp16 flash attention, lazy-rescale FA2, W never touches smem.
//   Rescale only when tile max exceeds running ref by > SLACK (w <= 2^SLACK,
//   fp16-safe). Reference updated to true max on trigger -> softmax exact.
// ============================================================================
#define HSTR   144
#define H_TILE (64 * HSTR)          // 9216
#define OFF_H0 0
#define OFF_H1 H_TILE
#define OFF_F0 (2 * H_TILE)
#define OFF_F1 (2 * H_TILE + 1024)
#define SMEM_SZ (2 * H_TILE + 2048) // 20480
#define SLACK  8.0f

__global__ __launch_bounds__(THREADS, 2) void attn_kernel(
    const float* __restrict__ x,
    const float* __restrict__ gamma,
    float* __restrict__ out)
{
    __shared__ __align__(128) char smem[SMEM_SZ];
    uint32_t sb = smem_u32(smem);

    int t = threadIdx.x;
    int wid = t >> 5, lane = t & 31;
    int b  = blockIdx.x >> 5;
    int mt = (blockIdx.x & 31) * TMC;
    int mw = mt + wid * 16;
    int r = lane >> 2, q = lane & 3;

    uint32_t hoff = (uint32_t)((lane & 15) * HSTR + (lane >> 4) * 16);

    uint32_t ga0, ga1;
    {
        const uint32_t* gp =
            (const uint32_t*)(g_g16 + ((size_t)b * NN_ + mw) * CQ);
        ga0 = gp[r * 4 + q];
        ga1 = gp[(r + 8) * 4 + q];
    }

    float acc[8][4];
    #pragma unroll
    for (int c = 0; c < 8; c++)
        #pragma unroll
        for (int i = 0; i < 4; i++) acc[c][i] = 0.0f;
    ull l2[2] = {0ULL, 0ULL};
    float m0 = -1e30f, m1 = -1e30f;   // running row refs (rows r, r+8)

    const unsigned short* hsrc0 = g_h16 + (size_t)b * NN_ * CC;
    const unsigned short* fsrc0 = g_f16 + (size_t)b * NN_ * CQ;

    auto load_tile = [&](int it) {
        int n0 = it * TN;
        uint32_t hb = sb + ((it & 1) ? OFF_H1 : OFF_H0);
        uint32_t fb = sb + ((it & 1) ? OFF_F1 : OFF_F0);
        #pragma unroll
        for (int p = 0; p < 2; p++) {
            int id = t + p * THREADS;
            int row = id >> 3, ch = id & 7;
            CPA16(hb + row * HSTR + ch * 16,
                  hsrc0 + ((size_t)(n0 + row)) * CC + ch * 8);
        }
        if (t < 64)
            CPA16(fb + t * 16, fsrc0 + ((size_t)(n0 + t)) * CQ);
        CPCOMMIT();
    };

    load_tile(0);

    for (int it = 0; it < NT; it++) {
        CPWAIT0();
        __syncthreads();
        if (it + 1 < NT) load_tile(it + 1);

        uint32_t hb = sb + ((it & 1) ? OFF_H1 : OFF_H0);
        uint32_t fb = sb + ((it & 1) ? OFF_F1 : OFF_F0);

        // ---- GEMM1: S[16m x 64n], f16 K=8 ----
        uint32_t fbr[8];
        ldsm4(fbr[0], fbr[1], fbr[2], fbr[3], fb + lane * 16);
        ldsm4(fbr[4], fbr[5], fbr[6], fbr[7], fb + 512 + lane * 16);
        float s[8][4];
        #pragma unroll
        for (int j = 0; j < 8; j++) {
            #pragma unroll
            for (int i = 0; i < 4; i++) s[j][i] = 0.0f;
            mma_k8(s[j], ga0, ga1, fbr[j]);
        }

        // ---- per-row tile max; rescale only if ref exceeded by > SLACK ----
        float t0 = -1e30f, t1 = -1e30f;
        #pragma unroll
        for (int j = 0; j < 8; j++) {
            t0 = fmaxf(t0, fmaxf(s[j][0], s[j][1]));
            t1 = fmaxf(t1, fmaxf(s[j][2], s[j][3]));
        }
        t0 = fmaxf(t0, __shfl_xor_sync(0xFFFFFFFF, t0, 1));
        t0 = fmaxf(t0, __shfl_xor_sync(0xFFFFFFFF, t0, 2));
        t1 = fmaxf(t1, __shfl_xor_sync(0xFFFFFFFF, t1, 1));
        t1 = fmaxf(t1, __shfl_xor_sync(0xFFFFFFFF, t1, 2));
        bool need = (t0 > m0 + SLACK) || (t1 > m1 + SLACK);
        if (__any_sync(0xFFFFFFFF, need)) {
            float m0n = fmaxf(m0, t0);
            float m1n = fmaxf(m1, t1);
            float sc0 = exp2s(m0 - m0n);
            float sc1 = exp2s(m1 - m1n);
            m0 = m0n; m1 = m1n;
            l2[0] = mul2(l2[0], pack2f(sc0, sc0));
            l2[1] = mul2(l2[1], pack2f(sc1, sc1));
            #pragma unroll
            for (int c = 0; c < 8; c++) {
                acc[c][0] *= sc0; acc[c][1] *= sc0;
                acc[c][2] *= sc1; acc[c][3] *= sc1;
            }
        }

        // ---- exp2(s - m) -> fp16 A-fragments in registers ----
        ull nm0 = pack2f(-m0, -m0);
        ull nm1 = pack2f(-m1, -m1);
        uint32_t af[4][4];
        #pragma unroll
        for (int tk = 0; tk < 4; tk++) {
            #pragma unroll
            for (int u = 0; u < 2; u++) {
                int j = 2 * tk + u;
                ull w01 = exp2_pair(add2(pack2f(s[j][0], s[j][1]), nm0));
                ull w23 = exp2_pair(add2(pack2f(s[j][2], s[j][3]), nm1));
                l2[0] = add2(l2[0], w01);
                l2[1] = add2(l2[1], w23);
                float wa, wb;
                unpack2f(w01, wa, wb);
                af[tk][2 * u]     = h2pack(wa, wb);
                unpack2f(w23, wa, wb);
                af[tk][2 * u + 1] = h2pack(wa, wb);
            }
        }

        // ---- GEMM2: O += W x H, f16 K=16, H via ldsm.trans ----
        #pragma unroll
        for (int tk = 0; tk < 4; tk++) {
            uint32_t hbase = hb + tk * 16 * HSTR + hoff;
            #pragma unroll
            for (int cb = 0; cb < 4; cb++) {
                uint32_t b0, b1, b2, b3;
                ldsm4t(b0, b1, b2, b3, hbase + cb * 32);
                mma_k16(acc[2 * cb],     af[tk], b0, b1);
                mma_k16(acc[2 * cb + 1], af[tk], b2, b3);
            }
        }
    }

    // ---- l reduction (warp-local quad) ----
    float scale0, scale1;
    {
        float gm = gamma[0];
        float lo, hi;
        unpack2f(l2[0], lo, hi);
        float la = lo + hi;
        la += __shfl_xor_sync(0xFFFFFFFF, la, 1);
        la += __shfl_xor_sync(0xFFFFFFFF, la, 2);
        unpack2f(l2[1], lo, hi);
        float lb = lo + hi;
        lb += __shfl_xor_sync(0xFFFFFFFF, lb, 1);
        lb += __shfl_xor_sync(0xFFFFFFFF, lb, 2);
        scale0 = gm / la;
        scale1 = gm / lb;
    }

    // ---- epilogue ----
    const float* xb = x   + (size_t)b * CC * NN_;
    float*       ob = out + (size_t)b * CC * NN_;
    int m0g = mw + r;
    #pragma unroll
    for (int cs = 0; cs < 8; cs++) {
        int c = cs * 8 + 2 * q;
        size_t a00 = (size_t)c * NN_ + m0g;
        size_t a01 = a00 + NN_;
        ob[a00]     = fmaf(acc[cs][0], scale0, xb[a00]);
        ob[a01]     = fmaf(acc[cs][1], scale0, xb[a01]);
        ob[a00 + 8] = fmaf(acc[cs][2], scale1, xb[a00 + 8]);
        ob[a01 + 8] = fmaf(acc[cs][3], scale1, xb[a01 + 8]);
    }
}

// ============================================================================
extern "C" void kernel_launch(void* const* d_in, const int* in_sizes, int n_in,
                              void* d_out, int out_size)
{
    const float* x     = (const float*)d_in[0];
    const float* Wq    = (const float*)d_in[1];
    const float* bq    = (const float*)d_in[2];
    const float* Wk    = (const float*)d_in[3];
    const float* bk    = (const float*)d_in[4];
    const float* Wv    = (const float*)d_in[5];
    const float* bv    = (const float*)d_in[6];
    const float* gamma = (const float*)d_in[7];
    float* out = (float*)d_out;

    proj_kernel<<<BATCH * NN_ / 128, 128>>>(x, Wq, bq, Wk, bk, Wv, bv);
    attn_kernel<<<BATCH * NN_ / TMC, THREADS>>>(x, gamma, out);
}